// round 6
// baseline (speedup 1.0000x reference)
#include <cuda_runtime.h>
#include <cuda_bf16.h>
#include <cstdint>

// Fixed shape: hidden_vectors (1024, 512) f32, labels (1024,) i32.
#define N 1024
#define D 512
#define CB 8            // column blocks of 128
#define RB 16           // row blocks of 64
#define GRID (CB * RB)  // 128
#define BK 64           // k-chunk per mainloop iter (8 iters)
#define ASTR 72         // smem row stride in bf16 (144B): banks 4r mod 32, conflict-free
#define NP 6            // power sums A0..A2, B0..B2 (softplus Taylor through x^2)

__device__ float g_partial[NP * CB * N];   // [p][cb][row]
__device__ unsigned g_ctr = 0;

__device__ __forceinline__ float sq4(float4 v) {
    return v.x * v.x + v.y * v.y + v.z * v.z + v.w * v.w;
}
__device__ __forceinline__ void st8(__nv_bfloat16* p, float4 v0, float4 v1) {
    __nv_bfloat162 t[4];
    t[0] = __floats2bfloat162_rn(v0.x, v0.y);
    t[1] = __floats2bfloat162_rn(v0.z, v0.w);
    t[2] = __floats2bfloat162_rn(v1.x, v1.y);
    t[3] = __floats2bfloat162_rn(v1.z, v1.w);
    *(uint4*)p = *(uint4*)t;
}
__device__ __forceinline__ void ldsm4(uint32_t* r, uint32_t addr) {
    asm volatile("ldmatrix.sync.aligned.m8n8.x4.shared.b16 {%0,%1,%2,%3},[%4];"
                 : "=r"(r[0]), "=r"(r[1]), "=r"(r[2]), "=r"(r[3]) : "r"(addr));
}

#define RED4(x) { x += __shfl_xor_sync(0xffffffffu, x, 1); \
                  x += __shfl_xor_sync(0xffffffffu, x, 2); }
#define RED8(x) { x += __shfl_xor_sync(0xffffffffu, x, 1); \
                  x += __shfl_xor_sync(0xffffffffu, x, 2); \
                  x += __shfl_xor_sync(0xffffffffu, x, 4); }

// ---------------------------------------------------------------------------
// One fused kernel. 512 threads = 16 warps (4 row x 4 col), tile 64x128,
// grid 128, BK=64 (8 iterations -> 8 barriers).
//  - raw f32 tiles, sum-of-squares on the fly (invnorm folded into epilogue)
//  - double-buffered smem, ldmatrix.x4, mma m16n8k16 bf16->f32
//  - epilogue: per-row power sums A_p (pos, sim/5), B_p (neg, sim/10), p=0..2
//  - last-block (threadfence + atomic counter; fixed reduction order) applies
//      softplus(x) = ln2 + x/2 + x^2/8     (x = b-a, sigma ~ 0.01; dropped
//      x^4/192 contributes ~1e-10 relative)
// ---------------------------------------------------------------------------
__global__ void __launch_bounds__(512, 1) kfused(const float* __restrict__ x,
                                                 const int* __restrict__ labels,
                                                 float* __restrict__ out) {
    __shared__ __align__(16) __nv_bfloat16 As[2][64 * ASTR];
    __shared__ __align__(16) __nv_bfloat16 Bs[2][128 * ASTR];
    __shared__ float invA[64];
    __shared__ float invB[128];
    __shared__ int lbli[64];
    __shared__ int lblj[128];
    __shared__ float part[4][64][NP];
    __shared__ float fs[512], fc[512];
    __shared__ int isLast;

    const int tid = threadIdx.x;
    const int wid = tid >> 5, lane = tid & 31;
    const int wr = (wid & 3) * 16;     // warp row base (0,16,32,48)
    const int wn = wid >> 2;           // col group 0..3
    const int wc = wn * 32;            // warp col base
    const int cb = blockIdx.x & (CB - 1);
    const int rb = blockIdx.x >> 3;
    const int bi = rb * 64, bj = cb * 128;

    if (tid < 64) lbli[tid] = labels[bi + tid];
    else if (tid < 192) lblj[tid - 64] = labels[bj + tid - 64];

    // global load mapping:
    //   A: thread t -> row t>>3 (0..63),  seg (t&7)*8 floats (2 float4)
    //   B: thread t -> row t>>2 (0..127), seg (t&3)*16 floats (4 float4)
    const int rowA = tid >> 3;
    const int segA = (tid & 7) * 8;
    const int rowB = tid >> 2;
    const int segB = (tid & 3) * 16;
    const float* Ap = x + (size_t)(bi + rowA) * D + segA;
    const float* Bp = x + (size_t)(bj + rowB) * D + segB;

    // ldmatrix bases (bytes)
    const uint32_t sA = (uint32_t)__cvta_generic_to_shared(&As[0][0]);
    const uint32_t sB = (uint32_t)__cvta_generic_to_shared(&Bs[0][0]);
    const uint32_t aBase = sA + (uint32_t)((wr + (lane & 15)) * ASTR + (lane >> 4) * 8) * 2u;
    const uint32_t bBase = sB + (uint32_t)((wc + lane) * ASTR) * 2u;
    const uint32_t aBuf = 64u * ASTR * 2u;
    const uint32_t bBuf = 128u * ASTR * 2u;

    float ssA = 0.f, ssB = 0.f;
    float acc[4][4];
#pragma unroll
    for (int nt = 0; nt < 4; nt++)
#pragma unroll
        for (int q = 0; q < 4; q++) acc[nt][q] = 0.f;

    // preload chunk 0
    float4 a0 = *(const float4*)(Ap),     a1 = *(const float4*)(Ap + 4);
    float4 b0 = *(const float4*)(Bp),     b1 = *(const float4*)(Bp + 4);
    float4 b2 = *(const float4*)(Bp + 8), b3 = *(const float4*)(Bp + 12);
    ssA += sq4(a0) + sq4(a1);
    ssB += sq4(b0) + sq4(b1) + sq4(b2) + sq4(b3);
    st8(&As[0][rowA * ASTR + segA], a0, a1);
    st8(&Bs[0][rowB * ASTR + segB], b0, b1);
    st8(&Bs[0][rowB * ASTR + segB + 8], b2, b3);
    __syncthreads();

#pragma unroll 1
    for (int i = 0; i < D / BK; i++) {
        const int cur = i & 1;
        if (i < D / BK - 1) {
            const int off = (i + 1) * BK;
            a0 = *(const float4*)(Ap + off);      a1 = *(const float4*)(Ap + off + 4);
            b0 = *(const float4*)(Bp + off);      b1 = *(const float4*)(Bp + off + 4);
            b2 = *(const float4*)(Bp + off + 8);  b3 = *(const float4*)(Bp + off + 12);
        }
        const uint32_t aB = aBase + cur * aBuf;
        const uint32_t bB = bBase + cur * bBuf;
#pragma unroll
        for (int ks = 0; ks < BK / 16; ks++) {
            uint32_t a[4], p0[4], p1[4];
            ldsm4(a, aB + ks * 32u);
            ldsm4(p0, bB + ks * 32u);
            ldsm4(p1, bB + ks * 32u + 16u);
#pragma unroll
            for (int nt = 0; nt < 4; nt++) {
                asm volatile(
                    "mma.sync.aligned.m16n8k16.row.col.f32.bf16.bf16.f32 "
                    "{%0,%1,%2,%3},{%4,%5,%6,%7},{%8,%9},{%0,%1,%2,%3};"
                    : "+f"(acc[nt][0]), "+f"(acc[nt][1]),
                      "+f"(acc[nt][2]), "+f"(acc[nt][3])
                    : "r"(a[0]), "r"(a[1]), "r"(a[2]), "r"(a[3]),
                      "r"(p0[nt]), "r"(p1[nt]));
            }
        }
        if (i < D / BK - 1) {
            ssA += sq4(a0) + sq4(a1);
            ssB += sq4(b0) + sq4(b1) + sq4(b2) + sq4(b3);
            const int nxt = cur ^ 1;
            st8(&As[nxt][rowA * ASTR + segA], a0, a1);
            st8(&Bs[nxt][rowB * ASTR + segB], b0, b1);
            st8(&Bs[nxt][rowB * ASTR + segB + 8], b2, b3);
            __syncthreads();
        }
    }

    // per-row inverse norms (A: 8 threads/row, B: 4 threads/row)
    RED8(ssA) RED4(ssB)
    if ((tid & 7) == 0) invA[rowA] = rsqrtf(ssA);
    if ((tid & 3) == 0) invB[rowB] = rsqrtf(ssB);
    __syncthreads();

    // ---- epilogue: fold acc into power sums ----
#pragma unroll
    for (int hf = 0; hf < 2; hf++) {
        const int lr = wr + hf * 8 + (lane >> 2);
        const int gr = bi + lr;
        const int li = lbli[lr];
        const float ia = invA[lr];
        float A0 = 0, A1 = 0, A2 = 0;
        float B0 = 0, B1 = 0, B2 = 0;
#pragma unroll
        for (int nt = 0; nt < 4; nt++)
#pragma unroll
            for (int cc = 0; cc < 2; cc++) {
                const int lc = wc + nt * 8 + (lane & 3) * 2 + cc;
                const float s = acc[nt][hf * 2 + cc] * ia * invB[lc];
                if (bj + lc != gr) {
                    if (lblj[lc] == li) {
                        float a = s * 0.2f;          // sim / TEMP_POS
                        A0 += 1.f; A1 += a; A2 += a * a;
                    } else {
                        float b = s * 0.1f;          // sim / TEMP_NEG
                        B0 += 1.f; B1 += b; B2 += b * b;
                    }
                }
            }
        RED4(A0) RED4(A1) RED4(A2) RED4(B0) RED4(B1) RED4(B2)
        if ((lane & 3) == 0) {
            float* d = &part[wn][lr][0];
            d[0] = A0; d[1] = A1; d[2] = A2;
            d[3] = B0; d[4] = B1; d[5] = B2;
        }
    }
    __syncthreads();

    // combine 4 column-warp partials, coalesced write [p][cb][row]
    for (int e = tid; e < NP * 64; e += 512) {
        const int p = e >> 6, lr = e & 63;
        float s = part[0][lr][p] + part[1][lr][p] + part[2][lr][p] + part[3][lr][p];
        g_partial[p * (CB * N) + cb * N + (bi + lr)] = s;
    }
    __syncthreads();
    __threadfence();

    // last-block election (counter monotonic; mod GRID valid across graph replays)
    if (tid == 0) {
        unsigned old = atomicAdd(&g_ctr, 1u);
        isLast = (((old + 1) & (GRID - 1)) == 0) ? 1 : 0;
    }
    __syncthreads();
    if (!isLast) return;
    __threadfence();

    // ---- final reduction (one block, fixed order -> deterministic) ----
    float ls = 0.f, lc = 0.f;
    for (int r = tid; r < N; r += 512) {
        float S[NP];
#pragma unroll
        for (int p = 0; p < NP; p++) {
            float s = 0.f;
#pragma unroll
            for (int c = 0; c < CB; c++) s += g_partial[p * (CB * N) + c * N + r];
            S[p] = s;
        }
        const float A0 = S[0], A1 = S[1], A2 = S[2];
        const float B0 = S[3], B1 = S[4], B2 = S[5];
        const float LN2 = 0.69314718055994530942f;
        float T = LN2 * A0 * B0
                + 0.5f * (B1 * A0 - A1 * B0)
                + 0.125f * (B2 * A0 - 2.f * A1 * B1 + A2 * B0);
        float npairs = A0 * B0;
        ls += (A0 > 0.f) ? (T / fmaxf(npairs, 1.f)) : 0.f;
        lc += (A0 > 0.f) ? 1.f : 0.f;
    }
    fs[tid] = ls; fc[tid] = lc;
    __syncthreads();
    for (int o = 256; o; o >>= 1) {
        if (tid < o) { fs[tid] += fs[tid + o]; fc[tid] += fc[tid + o]; }
        __syncthreads();
    }
    if (tid == 0)
        out[0] = (fc[0] > 0.f) ? (fs[0] / fmaxf(fc[0], 1.f)) : 0.f;
}

// ---------------------------------------------------------------------------
extern "C" void kernel_launch(void* const* d_in, const int* in_sizes, int n_in,
                              void* d_out, int out_size) {
    const float* hidden = (const float*)d_in[0];
    const int* labels = (const int*)d_in[1];
    float* out = (float*)d_out;
    kfused<<<GRID, 512>>>(hidden, labels, out);
}

// round 8
// speedup vs baseline: 1.1218x; 1.1218x over previous
#include <cuda_runtime.h>
#include <cuda_bf16.h>
#include <cstdint>

// Fixed shape: hidden_vectors (1024, 512) f32, labels (1024,) i32.
#define N 1024
#define D 512
#define TB 64           // square tile
#define NTILE 16        // 16x16 tile grid
#define GRID 136        // lower triangle incl diagonal: 16*17/2
#define ASTR 40         // smem row stride in bf16 (80B): LDSM rows conflict-free
#define NP 6            // power sums A0..A2, B0..B2 (softplus Taylor through x^2)

__device__ float g_partial[NP * NTILE * N];   // [p][colblock][row]
__device__ unsigned g_ctr = 0;

__device__ __forceinline__ float sq4(float4 v) {
    return v.x * v.x + v.y * v.y + v.z * v.z + v.w * v.w;
}
__device__ __forceinline__ void st4(__nv_bfloat16* p, float4 v) {
    __nv_bfloat162 t[2];
    t[0] = __floats2bfloat162_rn(v.x, v.y);
    t[1] = __floats2bfloat162_rn(v.z, v.w);
    *(uint2*)p = *(uint2*)t;
}
__device__ __forceinline__ void ldsm4(uint32_t* r, uint32_t addr) {
    asm volatile("ldmatrix.sync.aligned.m8n8.x4.shared.b16 {%0,%1,%2,%3},[%4];"
                 : "=r"(r[0]), "=r"(r[1]), "=r"(r[2]), "=r"(r[3]) : "r"(addr));
}

#define RED4(x)  { x += __shfl_xor_sync(0xffffffffu, x, 1); \
                   x += __shfl_xor_sync(0xffffffffu, x, 2); }
#define RED8(x)  { x += __shfl_xor_sync(0xffffffffu, x, 1); \
                   x += __shfl_xor_sync(0xffffffffu, x, 2); \
                   x += __shfl_xor_sync(0xffffffffu, x, 4); }
#define REDC(x)  { x += __shfl_xor_sync(0xffffffffu, x, 4); \
                   x += __shfl_xor_sync(0xffffffffu, x, 8); \
                   x += __shfl_xor_sync(0xffffffffu, x, 16); }

// ---------------------------------------------------------------------------
// One fused kernel exploiting sim symmetry: only the lower triangle of the
// 16x16 grid of 64x64 tiles is computed (136 blocks). Each off-diagonal tile
// (R,C) emits BOTH row partials (rows of R, colblock C) and transposed column
// partials (rows of C, colblock R) -- each sim value contributes identically
// to both endpoint rows' power sums.
//  - 512 threads = 16 warps (4 row x 4 col), warp tile 16x16
//  - raw f32 tiles, sum-of-squares fused (invnorm applied in epilogue)
//  - double-buffered smem, ldmatrix.x4, mma m16n8k16 bf16->f32
//  - power sums A_p (pos, sim/5), B_p (neg, sim/10), p=0..2
//  - last block applies softplus(x) = ln2 + x/2 + x^2/8 closed form
//    (x = b-a, sigma ~ 0.01; dropped x^4/192 term ~1e-10 relative)
// ---------------------------------------------------------------------------
__global__ void __launch_bounds__(512, 1) kfused(const float* __restrict__ x,
                                                 const int* __restrict__ labels,
                                                 float* __restrict__ out) {
    __shared__ __align__(16) __nv_bfloat16 As[2][TB * ASTR];
    __shared__ __align__(16) __nv_bfloat16 Bs[2][TB * ASTR];
    __shared__ float invA[TB];
    __shared__ float invB[TB];
    __shared__ int lbli[TB];
    __shared__ int lblj[TB];
    __shared__ float part[4][TB][NP];    // row partials, per col-warp group
    __shared__ float partT[4][TB][NP];   // col partials, per row-warp group
    __shared__ float fs[512], fc[512];
    __shared__ int isLast;

    const int tid = threadIdx.x;
    const int wid = tid >> 5, lane = tid & 31;
    const int wm = wid & 3;            // row-warp group
    const int wn = wid >> 2;           // col-warp group
    const int wr = wm * 16;
    const int wc = wn * 16;

    // triangular decode: block b -> (rb, cb), cb <= rb
    int rb = 0;
    {
        int b = blockIdx.x;
        while ((rb + 1) * (rb + 2) / 2 <= b) rb++;
    }
    const int cb = blockIdx.x - rb * (rb + 1) / 2;
    const int bi = rb * TB, bj = cb * TB;
    const bool offdiag = (rb != cb);

    if (tid < TB) lbli[tid] = labels[bi + tid];
    else if (tid < 2 * TB) lblj[tid - TB] = labels[bj + tid - TB];

    // global loads: thread t -> row t>>3 (0..63), seg (t&7)*4
    const int gr8 = tid >> 3;
    const int seg = (tid & 7) * 4;
    const float* Ap = x + (size_t)(bi + gr8) * D + seg;
    const float* Bp = x + (size_t)(bj + gr8) * D + seg;

    // ldmatrix bases
    const uint32_t sA = (uint32_t)__cvta_generic_to_shared(&As[0][0]);
    const uint32_t sB = (uint32_t)__cvta_generic_to_shared(&Bs[0][0]);
    const uint32_t aBase = sA + (uint32_t)((wr + (lane & 15)) * ASTR + (lane >> 4) * 8) * 2u;
    const uint32_t bBase = sB + (uint32_t)((wc + (lane & 15)) * ASTR + (lane >> 4) * 8) * 2u;
    const uint32_t buf = (uint32_t)(TB * ASTR) * 2u;

    float ssA = 0.f, ssB = 0.f;
    float acc[2][4];
#pragma unroll
    for (int nt = 0; nt < 2; nt++)
#pragma unroll
        for (int q = 0; q < 4; q++) acc[nt][q] = 0.f;

    // preload chunk 0
    float4 av = *(const float4*)(Ap);
    float4 bv = *(const float4*)(Bp);
    ssA += sq4(av); ssB += sq4(bv);
    st4(&As[0][gr8 * ASTR + seg], av);
    st4(&Bs[0][gr8 * ASTR + seg], bv);
    __syncthreads();

#pragma unroll 1
    for (int i = 0; i < 16; i++) {
        const int cur = i & 1;
        if (i < 15) {
            const int off = (i + 1) * 32;
            av = *(const float4*)(Ap + off);
            bv = *(const float4*)(Bp + off);
        }
        const uint32_t aB = aBase + cur * buf;
        const uint32_t bB = bBase + cur * buf;
#pragma unroll
        for (int ks = 0; ks < 2; ks++) {
            uint32_t a[4], b[4];
            ldsm4(a, aB + ks * 32u);
            ldsm4(b, bB + ks * 32u);
            // b regs: r0=(n0-7,k0) r1=(n8-15,k0) r2=(n0-7,k8) r3=(n8-15,k8)
            asm volatile(
                "mma.sync.aligned.m16n8k16.row.col.f32.bf16.bf16.f32 "
                "{%0,%1,%2,%3},{%4,%5,%6,%7},{%8,%9},{%0,%1,%2,%3};"
                : "+f"(acc[0][0]), "+f"(acc[0][1]), "+f"(acc[0][2]), "+f"(acc[0][3])
                : "r"(a[0]), "r"(a[1]), "r"(a[2]), "r"(a[3]), "r"(b[0]), "r"(b[2]));
            asm volatile(
                "mma.sync.aligned.m16n8k16.row.col.f32.bf16.bf16.f32 "
                "{%0,%1,%2,%3},{%4,%5,%6,%7},{%8,%9},{%0,%1,%2,%3};"
                : "+f"(acc[1][0]), "+f"(acc[1][1]), "+f"(acc[1][2]), "+f"(acc[1][3])
                : "r"(a[0]), "r"(a[1]), "r"(a[2]), "r"(a[3]), "r"(b[1]), "r"(b[3]));
        }
        if (i < 15) {
            ssA += sq4(av); ssB += sq4(bv);
            const int nxt = cur ^ 1;
            st4(&As[nxt][gr8 * ASTR + seg], av);
            st4(&Bs[nxt][gr8 * ASTR + seg], bv);
            __syncthreads();
        }
    }

    // per-row inverse norms (8 threads per row)
    RED8(ssA) RED8(ssB)
    if ((tid & 7) == 0) {
        invA[gr8] = rsqrtf(ssA);
        invB[gr8] = rsqrtf(ssB);
    }
    __syncthreads();

    // ---- epilogue: row power sums + (off-diag) column power sums ----
    float cA0[4] = {0, 0, 0, 0}, cA1[4] = {0, 0, 0, 0}, cA2[4] = {0, 0, 0, 0};
    float cB0[4] = {0, 0, 0, 0}, cB1[4] = {0, 0, 0, 0}, cB2[4] = {0, 0, 0, 0};

#pragma unroll
    for (int hf = 0; hf < 2; hf++) {
        const int lr = wr + hf * 8 + (lane >> 2);
        const int gr = bi + lr;
        const int li = lbli[lr];
        const float ia = invA[lr];
        float A0 = 0, A1 = 0, A2 = 0;
        float B0 = 0, B1 = 0, B2 = 0;
#pragma unroll
        for (int nt = 0; nt < 2; nt++)
#pragma unroll
            for (int cc = 0; cc < 2; cc++) {
                const int lc = wc + nt * 8 + (lane & 3) * 2 + cc;
                const int q = nt * 2 + cc;
                const float s = acc[nt][hf * 2 + cc] * ia * invB[lc];
                if (bj + lc != gr) {
                    if (lblj[lc] == li) {
                        float a = s * 0.2f;          // sim / TEMP_POS
                        A0 += 1.f; A1 += a; A2 += a * a;
                        cA0[q] += 1.f; cA1[q] += a; cA2[q] += a * a;
                    } else {
                        float b = s * 0.1f;          // sim / TEMP_NEG
                        B0 += 1.f; B1 += b; B2 += b * b;
                        cB0[q] += 1.f; cB1[q] += b; cB2[q] += b * b;
                    }
                }
            }
        RED4(A0) RED4(A1) RED4(A2) RED4(B0) RED4(B1) RED4(B2)
        if ((lane & 3) == 0) {
            float* d = &part[wn][lr][0];
            d[0] = A0; d[1] = A1; d[2] = A2;
            d[3] = B0; d[4] = B1; d[5] = B2;
        }
    }

    if (offdiag) {
        // reduce column sums across the 8 lanes sharing each column
#pragma unroll
        for (int q = 0; q < 4; q++) {
            REDC(cA0[q]) REDC(cA1[q]) REDC(cA2[q])
            REDC(cB0[q]) REDC(cB1[q]) REDC(cB2[q])
        }
        if ((lane >> 2) == 0) {
#pragma unroll
            for (int q = 0; q < 4; q++) {
                const int nt = q >> 1, cc = q & 1;
                const int lc = wc + nt * 8 + lane * 2 + cc;
                float* d = &partT[wm][lc][0];
                d[0] = cA0[q]; d[1] = cA1[q]; d[2] = cA2[q];
                d[3] = cB0[q]; d[4] = cB1[q]; d[5] = cB2[q];
            }
        }
    }
    __syncthreads();

    // combine partials, coalesced writes to g_partial [p][colblock][row]
    for (int e = tid; e < NP * TB; e += 512) {
        const int p = e >> 6, lr = e & 63;
        float s = part[0][lr][p] + part[1][lr][p] + part[2][lr][p] + part[3][lr][p];
        g_partial[p * (NTILE * N) + cb * N + (bi + lr)] = s;
    }
    if (offdiag) {
        for (int e = tid; e < NP * TB; e += 512) {
            const int p = e >> 6, lc = e & 63;
            float s = partT[0][lc][p] + partT[1][lc][p] + partT[2][lc][p] + partT[3][lc][p];
            g_partial[p * (NTILE * N) + rb * N + (bj + lc)] = s;
        }
    }
    __syncthreads();
    __threadfence();

    // last-block election (counter monotonic; mod GRID valid across graph replays)
    if (tid == 0) {
        unsigned old = atomicAdd(&g_ctr, 1u);
        isLast = (((old + 1) % GRID) == 0) ? 1 : 0;
    }
    __syncthreads();
    if (!isLast) return;
    __threadfence();

    // ---- final reduction (one block, fixed order -> deterministic) ----
    float ls = 0.f, lc2 = 0.f;
    for (int r = tid; r < N; r += 512) {
        float S[NP];
#pragma unroll
        for (int p = 0; p < NP; p++) {
            float s = 0.f;
#pragma unroll
            for (int c = 0; c < NTILE; c++) s += g_partial[p * (NTILE * N) + c * N + r];
            S[p] = s;
        }
        const float A0 = S[0], A1 = S[1], A2 = S[2];
        const float B0 = S[3], B1 = S[4], B2 = S[5];
        const float LN2 = 0.69314718055994530942f;
        float T = LN2 * A0 * B0
                + 0.5f * (B1 * A0 - A1 * B0)
                + 0.125f * (B2 * A0 - 2.f * A1 * B1 + A2 * B0);
        float npairs = A0 * B0;
        ls += (A0 > 0.f) ? (T / fmaxf(npairs, 1.f)) : 0.f;
        lc2 += (A0 > 0.f) ? 1.f : 0.f;
    }
    fs[tid] = ls; fc[tid] = lc2;
    __syncthreads();
    for (int o = 256; o; o >>= 1) {
        if (tid < o) { fs[tid] += fs[tid + o]; fc[tid] += fc[tid + o]; }
        __syncthreads();
    }
    if (tid == 0)
        out[0] = (fc[0] > 0.f) ? (fs[0] / fmaxf(fc[0], 1.f)) : 0.f;
}

// ---------------------------------------------------------------------------
extern "C" void kernel_launch(void* const* d_in, const int* in_sizes, int n_in,
                              void* d_out, int out_size) {
    const float* hidden = (const float*)d_in[0];
    const int* labels = (const int*)d_in[1];
    float* out = (float*)d_out;
    kfused<<<GRID, 512>>>(hidden, labels, out);
}

// round 9
// speedup vs baseline: 1.2557x; 1.1193x over previous
#include <cuda_runtime.h>
#include <cuda_bf16.h>
#include <cstdint>

// Fixed shape: hidden_vectors (1024, 512) f32, labels (1024,) i32.
#define N 1024
#define D 512
#define TB 64           // square tile
#define NTILE 16        // 16x16 tile grid
#define GRID 136        // lower triangle incl diagonal: 16*17/2
#define ASTR 40         // smem row stride in bf16 (80B): LDSM rows conflict-free
#define NP 6            // power sums A0..A2, B0..B2 (softplus Taylor through x^2)
#define NCH 16          // k chunks of 32
#define CHB (TB * ASTR * 2)       // 5120 bytes per chunk tile
#define ABYTES (NCH * CHB)        // 81920
#define SMEMB (2 * ABYTES)        // 160 KB dynamic

__device__ float g_partial[NP * NTILE * N];   // [p][colblock][row]
__device__ unsigned g_ctr = 0;

__device__ __forceinline__ float sq4(float4 v) {
    return v.x * v.x + v.y * v.y + v.z * v.z + v.w * v.w;
}
__device__ __forceinline__ void st4(__nv_bfloat16* p, float4 v) {
    __nv_bfloat162 t[2];
    t[0] = __floats2bfloat162_rn(v.x, v.y);
    t[1] = __floats2bfloat162_rn(v.z, v.w);
    *(uint2*)p = *(uint2*)t;
}
__device__ __forceinline__ void ldsm4(uint32_t* r, uint32_t addr) {
    asm volatile("ldmatrix.sync.aligned.m8n8.x4.shared.b16 {%0,%1,%2,%3},[%4];"
                 : "=r"(r[0]), "=r"(r[1]), "=r"(r[2]), "=r"(r[3]) : "r"(addr));
}

#define RED4(x)  { x += __shfl_xor_sync(0xffffffffu, x, 1); \
                   x += __shfl_xor_sync(0xffffffffu, x, 2); }
#define RED8(x)  { x += __shfl_xor_sync(0xffffffffu, x, 1); \
                   x += __shfl_xor_sync(0xffffffffu, x, 2); \
                   x += __shfl_xor_sync(0xffffffffu, x, 4); }
#define REDC(x)  { x += __shfl_xor_sync(0xffffffffu, x, 4); \
                   x += __shfl_xor_sync(0xffffffffu, x, 8); \
                   x += __shfl_xor_sync(0xffffffffu, x, 16); }

// ---------------------------------------------------------------------------
// Single-barrier fused kernel. The whole K=512 extent is resident in smem
// (160 KB dynamic), so the mainloop has NO per-chunk barriers:
//   phase 1: 32 independent LDG.128/thread -> sumsq -> swizzled STS
//   phase 2: ONE __syncthreads
//   phase 3: 32 pure LDSM+MMA k-steps per warp (no joints)
// Triangular tile grid (136 blocks = 1 wave): off-diagonal tiles emit both
// row partials and transposed column partials (sim symmetry).
// Loss: softplus(x) = ln2 + x/2 + x^2/8 closed form over power sums
// (x = b-a, sigma ~ 0.01; dropped x^4/192 ~ 1e-10 relative).
// ---------------------------------------------------------------------------
__global__ void __launch_bounds__(512, 1) kfused(const float* __restrict__ x,
                                                 const int* __restrict__ labels,
                                                 float* __restrict__ out) {
    extern __shared__ __align__(16) unsigned char dyn[];
    __shared__ float invA[TB];
    __shared__ float invB[TB];
    __shared__ int lbli[TB];
    __shared__ int lblj[TB];
    __shared__ float part[4][TB][NP];    // row partials, per col-warp group
    __shared__ float partT[4][TB][NP];   // col partials, per row-warp group
    __shared__ float fs[512], fc[512];
    __shared__ int isLast;

    const int tid = threadIdx.x;
    const int wid = tid >> 5, lane = tid & 31;
    const int wm = wid & 3;            // row-warp group
    const int wn = wid >> 2;           // col-warp group
    const int wr = wm * 16;
    const int wc = wn * 16;

    // triangular decode: block b -> (rb, cb), cb <= rb
    int rb = 0;
    {
        int b = blockIdx.x;
        while ((rb + 1) * (rb + 2) / 2 <= b) rb++;
    }
    const int cb = blockIdx.x - rb * (rb + 1) / 2;
    const int bi = rb * TB, bj = cb * TB;
    const bool offdiag = (rb != cb);

    if (tid < TB) lbli[tid] = labels[bi + tid];
    else if (tid < 2 * TB) lblj[tid - TB] = labels[bj + tid - TB];

    // global loads: thread t -> row t>>3 (0..63), seg (t&7)*4 f32 within chunk
    const int gr8 = tid >> 3;
    const int seg = (tid & 7) * 4;
    const float* Ap = x + (size_t)(bi + gr8) * D + seg;
    const float* Bp = x + (size_t)(bj + gr8) * D + seg;
    const uint32_t stoff = (uint32_t)(gr8 * ASTR + seg);   // bf16 elems

    float ssA = 0.f, ssB = 0.f;

    // ---- phase 1: load everything (no barriers; chunks go to disjoint smem) ----
#pragma unroll 4
    for (int i = 0; i < NCH; i++) {
        float4 av = *(const float4*)(Ap + i * 32);
        float4 bv = *(const float4*)(Bp + i * 32);
        ssA += sq4(av); ssB += sq4(bv);
        st4((__nv_bfloat16*)(dyn + i * CHB) + stoff, av);
        st4((__nv_bfloat16*)(dyn + ABYTES + i * CHB) + stoff, bv);
    }

    // per-row inverse norms (8 threads per row) -- before the single barrier
    RED8(ssA) RED8(ssB)
    if ((tid & 7) == 0) {
        invA[gr8] = rsqrtf(ssA);
        invB[gr8] = rsqrtf(ssB);
    }
    __syncthreads();   // the ONE barrier

    // ---- phase 2: pure MMA stream ----
    const uint32_t sBase = (uint32_t)__cvta_generic_to_shared(dyn);
    const uint32_t aOff = (uint32_t)((wr + (lane & 15)) * ASTR + (lane >> 4) * 8) * 2u;
    const uint32_t bOff = (uint32_t)ABYTES +
                          (uint32_t)((wc + (lane & 15)) * ASTR + (lane >> 4) * 8) * 2u;

    float acc[2][4];
#pragma unroll
    for (int nt = 0; nt < 2; nt++)
#pragma unroll
        for (int q = 0; q < 4; q++) acc[nt][q] = 0.f;

#pragma unroll
    for (int i = 0; i < NCH; i++) {
#pragma unroll
        for (int ks = 0; ks < 2; ks++) {
            uint32_t a[4], b[4];
            ldsm4(a, sBase + aOff + i * CHB + ks * 32u);
            ldsm4(b, sBase + bOff + i * CHB + ks * 32u);
            // b regs: r0=(n0-7,k0) r1=(n8-15,k0) r2=(n0-7,k8) r3=(n8-15,k8)
            asm volatile(
                "mma.sync.aligned.m16n8k16.row.col.f32.bf16.bf16.f32 "
                "{%0,%1,%2,%3},{%4,%5,%6,%7},{%8,%9},{%0,%1,%2,%3};"
                : "+f"(acc[0][0]), "+f"(acc[0][1]), "+f"(acc[0][2]), "+f"(acc[0][3])
                : "r"(a[0]), "r"(a[1]), "r"(a[2]), "r"(a[3]), "r"(b[0]), "r"(b[2]));
            asm volatile(
                "mma.sync.aligned.m16n8k16.row.col.f32.bf16.bf16.f32 "
                "{%0,%1,%2,%3},{%4,%5,%6,%7},{%8,%9},{%0,%1,%2,%3};"
                : "+f"(acc[1][0]), "+f"(acc[1][1]), "+f"(acc[1][2]), "+f"(acc[1][3])
                : "r"(a[0]), "r"(a[1]), "r"(a[2]), "r"(a[3]), "r"(b[1]), "r"(b[3]));
        }
    }

    // ---- epilogue: row power sums + (off-diag) column power sums ----
    float cA0[4] = {0, 0, 0, 0}, cA1[4] = {0, 0, 0, 0}, cA2[4] = {0, 0, 0, 0};
    float cB0[4] = {0, 0, 0, 0}, cB1[4] = {0, 0, 0, 0}, cB2[4] = {0, 0, 0, 0};

#pragma unroll
    for (int hf = 0; hf < 2; hf++) {
        const int lr = wr + hf * 8 + (lane >> 2);
        const int gr = bi + lr;
        const int li = lbli[lr];
        const float ia = invA[lr];
        float A0 = 0, A1 = 0, A2 = 0;
        float B0 = 0, B1 = 0, B2 = 0;
#pragma unroll
        for (int nt = 0; nt < 2; nt++)
#pragma unroll
            for (int cc = 0; cc < 2; cc++) {
                const int lc = wc + nt * 8 + (lane & 3) * 2 + cc;
                const int q = nt * 2 + cc;
                const float s = acc[nt][hf * 2 + cc] * ia * invB[lc];
                if (bj + lc != gr) {
                    if (lblj[lc] == li) {
                        float a = s * 0.2f;          // sim / TEMP_POS
                        A0 += 1.f; A1 += a; A2 += a * a;
                        cA0[q] += 1.f; cA1[q] += a; cA2[q] += a * a;
                    } else {
                        float b = s * 0.1f;          // sim / TEMP_NEG
                        B0 += 1.f; B1 += b; B2 += b * b;
                        cB0[q] += 1.f; cB1[q] += b; cB2[q] += b * b;
                    }
                }
            }
        RED4(A0) RED4(A1) RED4(A2) RED4(B0) RED4(B1) RED4(B2)
        if ((lane & 3) == 0) {
            float* d = &part[wn][lr][0];
            d[0] = A0; d[1] = A1; d[2] = A2;
            d[3] = B0; d[4] = B1; d[5] = B2;
        }
    }

    if (offdiag) {
#pragma unroll
        for (int q = 0; q < 4; q++) {
            REDC(cA0[q]) REDC(cA1[q]) REDC(cA2[q])
            REDC(cB0[q]) REDC(cB1[q]) REDC(cB2[q])
        }
        if ((lane >> 2) == 0) {
#pragma unroll
            for (int q = 0; q < 4; q++) {
                const int nt = q >> 1, cc = q & 1;
                const int lc = wc + nt * 8 + lane * 2 + cc;
                float* d = &partT[wm][lc][0];
                d[0] = cA0[q]; d[1] = cA1[q]; d[2] = cA2[q];
                d[3] = cB0[q]; d[4] = cB1[q]; d[5] = cB2[q];
            }
        }
    }
    __syncthreads();

    // combine partials, coalesced writes to g_partial [p][colblock][row]
    for (int e = tid; e < NP * TB; e += 512) {
        const int p = e >> 6, lr = e & 63;
        float s = part[0][lr][p] + part[1][lr][p] + part[2][lr][p] + part[3][lr][p];
        g_partial[p * (NTILE * N) + cb * N + (bi + lr)] = s;
    }
    if (offdiag) {
        for (int e = tid; e < NP * TB; e += 512) {
            const int p = e >> 6, lc = e & 63;
            float s = partT[0][lc][p] + partT[1][lc][p] + partT[2][lc][p] + partT[3][lc][p];
            g_partial[p * (NTILE * N) + rb * N + (bj + lc)] = s;
        }
    }
    __syncthreads();
    __threadfence();

    // last-block election (counter monotonic; mod GRID valid across graph replays)
    if (tid == 0) {
        unsigned old = atomicAdd(&g_ctr, 1u);
        isLast = (((old + 1) % GRID) == 0) ? 1 : 0;
    }
    __syncthreads();
    if (!isLast) return;
    __threadfence();

    // ---- final reduction (one block, fixed order -> deterministic) ----
    float ls = 0.f, lc2 = 0.f;
    for (int r = tid; r < N; r += 512) {
        float S[NP];
#pragma unroll
        for (int p = 0; p < NP; p++) {
            float s = 0.f;
#pragma unroll
            for (int c = 0; c < NTILE; c++) s += g_partial[p * (NTILE * N) + c * N + r];
            S[p] = s;
        }
        const float A0 = S[0], A1 = S[1], A2 = S[2];
        const float B0 = S[3], B1 = S[4], B2 = S[5];
        const float LN2 = 0.69314718055994530942f;
        float T = LN2 * A0 * B0
                + 0.5f * (B1 * A0 - A1 * B0)
                + 0.125f * (B2 * A0 - 2.f * A1 * B1 + A2 * B0);
        float npairs = A0 * B0;
        ls += (A0 > 0.f) ? (T / fmaxf(npairs, 1.f)) : 0.f;
        lc2 += (A0 > 0.f) ? 1.f : 0.f;
    }
    fs[tid] = ls; fc[tid] = lc2;
    __syncthreads();
    for (int o = 256; o; o >>= 1) {
        if (tid < o) { fs[tid] += fs[tid + o]; fc[tid] += fc[tid + o]; }
        __syncthreads();
    }
    if (tid == 0)
        out[0] = (fc[0] > 0.f) ? (fs[0] / fmaxf(fc[0], 1.f)) : 0.f;
}

// ---------------------------------------------------------------------------
extern "C" void kernel_launch(void* const* d_in, const int* in_sizes, int n_in,
                              void* d_out, int out_size) {
    const float* hidden = (const float*)d_in[0];
    const int* labels = (const int*)d_in[1];
    float* out = (float*)d_out;
    cudaFuncSetAttribute(kfused, cudaFuncAttributeMaxDynamicSharedMemorySize, SMEMB);
    kfused<<<GRID, 512, SMEMB>>>(hidden, labels, out);
}